// round 12
// baseline (speedup 1.0000x reference)
#include <cuda_runtime.h>
#include <cuda_bf16.h>
#include <math.h>
#include <stdint.h>

// Problem constants
#define B_    2
#define N_    1024
#define QD_   512
#define H_    8
#define DH_   64
#define SCALE_ 0.125f   // DH^-0.5
#define KVSPLIT 4

// ---------------- PTX helpers ----------------
__device__ __forceinline__ uint32_t smem_u32(const void* p) {
    uint32_t a;
    asm("{ .reg .u64 t; cvta.to.shared.u64 t, %1; cvt.u32.u64 %0, t; }" : "=r"(a) : "l"(p));
    return a;
}
__device__ __forceinline__ void cp16(uint32_t dst, const void* src) {
    asm volatile("cp.async.cg.shared.global [%0], [%1], 16;" :: "r"(dst), "l"(src) : "memory");
}
#define CP_COMMIT asm volatile("cp.async.commit_group;" ::: "memory")
#define CP_WAIT1  asm volatile("cp.async.wait_group 1;" ::: "memory")
#define CP_WAIT0  asm volatile("cp.async.wait_group 0;" ::: "memory")

__device__ __forceinline__ void ldsm4(uint32_t* r, uint32_t a) {
    asm volatile("ldmatrix.sync.aligned.m8n8.x4.shared.b16 {%0,%1,%2,%3}, [%4];"
                 : "=r"(r[0]), "=r"(r[1]), "=r"(r[2]), "=r"(r[3]) : "r"(a));
}
__device__ __forceinline__ void ldsm4t(uint32_t* r, uint32_t a) {
    asm volatile("ldmatrix.sync.aligned.m8n8.x4.trans.shared.b16 {%0,%1,%2,%3}, [%4];"
                 : "=r"(r[0]), "=r"(r[1]), "=r"(r[2]), "=r"(r[3]) : "r"(a));
}
__device__ __forceinline__ void mma16816(float* c, const uint32_t* a, uint32_t b0, uint32_t b1) {
    asm volatile(
        "mma.sync.aligned.m16n8k16.row.col.f32.bf16.bf16.f32 "
        "{%0,%1,%2,%3}, {%4,%5,%6,%7}, {%8,%9}, {%0,%1,%2,%3};"
        : "+f"(c[0]), "+f"(c[1]), "+f"(c[2]), "+f"(c[3])
        : "r"(a[0]), "r"(a[1]), "r"(a[2]), "r"(a[3]), "r"(b0), "r"(b1));
}
__device__ __forceinline__ uint32_t pkbf(float lo, float hi) {
    uint32_t r;
    asm("cvt.rn.satfinite.bf16x2.f32 %0, %1, %2;" : "=r"(r) : "f"(hi), "f"(lo));
    return r;
}
__device__ __forceinline__ float lo16f(uint32_t u) { return __uint_as_float(u << 16); }
__device__ __forceinline__ float hi16f(uint32_t u) { return __uint_as_float(u & 0xffff0000u); }

typedef __nv_bfloat16 bf;
typedef __nv_bfloat162 bf2;

// ---------------- scratch ----------------
__device__ float g_m [N_];
__device__ float g_cnt[1];
__device__ float g_scale[2*QD_];
__device__ float g_shift[2*QD_];
__device__ float g_padain[2*QD_*32*4];    // [tensor][ch][rowgrp(32)][4]
__device__ bf g_xhi[B_*N_*QD_], g_xlo[B_*N_*QD_];
__device__ bf g_whi[4][QD_*QD_], g_wlo[4][QD_*QD_];
__device__ bf g_qhi[B_*N_*QD_], g_qlo[B_*N_*QD_];
__device__ bf g_khi[B_*N_*QD_], g_klo[B_*N_*QD_];
__device__ bf g_vhi[B_*N_*QD_], g_vlo[B_*N_*QD_];
__device__ bf g_aohi[B_*N_*QD_], g_aolo[B_*N_*QD_];
__device__ float g_part[KVSPLIT*16*N_*DH_];
__device__ float g_lsum[KVSPLIT*16*N_];

// =================================================================
// fp32 -> bf16 hi/lo split helpers
// =================================================================
__device__ __forceinline__ void split2(float a, float b, bf2& h2, bf2& l2) {
    bf h0 = __float2bfloat16(a), h1 = __float2bfloat16(b);
    h2.x = h0; h2.y = h1;
    l2.x = __float2bfloat16(a - __bfloat162float(h0));
    l2.y = __float2bfloat16(b - __bfloat162float(h1));
}

// One fused conversion kernel: x (262144 f4) then W0..W3 (4 x 65536 f4)
__global__ __launch_bounds__(256) void cvt_all(
    const float4* __restrict__ x,
    const float4* __restrict__ w0, const float4* __restrict__ w1,
    const float4* __restrict__ w2, const float4* __restrict__ w3,
    bf2* __restrict__ xhi, bf2* __restrict__ xlo,
    bf2* __restrict__ whi, bf2* __restrict__ wlo)
{
    int i = blockIdx.x * 256 + threadIdx.x;      // [0, 524288)
    const float4* src;
    bf2 *hi, *lo;
    size_t o;
    if (i < 262144) {
        src = x + i; hi = xhi; lo = xlo; o = (size_t)i * 2;
    } else {
        int j = i - 262144;
        int t = j >> 16, jj = j & 65535;
        src = ((t == 0) ? w0 : (t == 1) ? w1 : (t == 2) ? w2 : w3) + jj;
        hi = whi; lo = wlo; o = (size_t)j * 2;
    }
    float4 v = *src;
    bf2 h0, l0, h1, l1;
    split2(v.x, v.y, h0, l0);
    split2(v.z, v.w, h1, l1);
    hi[o] = h0; hi[o+1] = h1;
    lo[o] = l0; lo[o+1] = l1;
}

// =================================================================
// mma.sync GEMM, tile 128x64, BK=32, 2-stage cp.async, split-bf16.
// smem 61440 + <=85 regs (launch_bounds 256,3) -> 3 CTAs/SM.
// MODE 0: fused QKV -> bf16 hi/lo; MODE 1: fp32 + bias.
// =================================================================
#define S_AH(s) ((s)*30720 + 0)
#define S_AL(s) ((s)*30720 + 10240)
#define S_BH(s) ((s)*30720 + 20480)
#define S_BL(s) ((s)*30720 + 25600)
#define GEMM_SMEM 61440

template<int MODE>
__global__ __launch_bounds__(256, 3) void gemm_mma(
    const bf* __restrict__ Ahi, const bf* __restrict__ Alo,
    const bf* __restrict__ Bhi, const bf* __restrict__ Blo,
    const float* __restrict__ bias, float* __restrict__ Cf,
    bf* __restrict__ O0h, bf* __restrict__ O0l,
    bf* __restrict__ O1h, bf* __restrict__ O1l,
    bf* __restrict__ O2h, bf* __restrict__ O2l,
    int M, int K)
{
    extern __shared__ __align__(16) char sg[];
    const uint32_t sb = smem_u32(sg);
    const int tid = threadIdx.x;
    const int warp = tid >> 5, lane = tid & 31;
    const int wm = warp & 3, wn = warp >> 2;
    const int bm = blockIdx.y * 128, bn = blockIdx.x * 64;
    const int grp = lane >> 3, lr = lane & 7;

    auto load_stage = [&](int s, int k0) {
#pragma unroll
        for (int i = 0; i < 4; i++) {
            int c = tid + i * 256;
            int p = c >> 9, r = (c >> 2) & 127, col = c & 3;
            const bf* src = (p ? Alo : Ahi) + (size_t)(bm + r) * K + k0 + col * 8;
            cp16(sb + (p ? S_AL(s) : S_AH(s)) + r * 80 + col * 16, src);
        }
#pragma unroll
        for (int i = 0; i < 2; i++) {
            int c = tid + i * 256;
            int p = c >> 8, r = (c >> 2) & 63, col = c & 3;
            const bf* src = (p ? Blo : Bhi) + (size_t)(bn + r) * K + k0 + col * 8;
            cp16(sb + (p ? S_BL(s) : S_BH(s)) + r * 80 + col * 16, src);
        }
    };

    float acc[32];
#pragma unroll
    for (int i = 0; i < 32; i++) acc[i] = 0.f;

    const int ksteps = K >> 5;   // 16 for K=512
    load_stage(0, 0);  CP_COMMIT;
    load_stage(1, 32); CP_COMMIT;

    const uint32_t aaddr = (wm * 32 + (lane & 15)) * 80 + (lane >> 4) * 16;
    const int rowB = wn * 32 + ((grp >> 1) << 3) + lr;
    const int colB = (grp & 1) * 16;

    for (int kt = 0; kt < ksteps; kt++) {
        if (kt == ksteps - 1) { CP_WAIT0; } else { CP_WAIT1; }
        __syncthreads();
        const int s = kt & 1;
        const uint32_t ahb = sb + S_AH(s), alb = sb + S_AL(s);
        const uint32_t bhb = sb + S_BH(s), blb = sb + S_BL(s);

#pragma unroll
        for (int kb = 0; kb < 2; kb++) {
            uint32_t ah[2][4], al[2][4];
#pragma unroll
            for (int mt = 0; mt < 2; mt++) {
                ldsm4(ah[mt], ahb + aaddr + mt * 16 * 80 + kb * 32);
                ldsm4(al[mt], alb + aaddr + mt * 16 * 80 + kb * 32);
            }
#pragma unroll
            for (int p = 0; p < 2; p++) {
                uint32_t bhf[4], blf[4];
                ldsm4(bhf, bhb + (rowB + p * 16) * 80 + kb * 32 + colB);
                ldsm4(blf, blb + (rowB + p * 16) * 80 + kb * 32 + colB);
#pragma unroll
                for (int mt = 0; mt < 2; mt++) {
#pragma unroll
                    for (int sub = 0; sub < 2; sub++) {
                        float* c = &acc[(mt * 4 + p * 2 + sub) * 4];
                        mma16816(c, ah[mt], bhf[sub * 2], bhf[sub * 2 + 1]);
                        mma16816(c, al[mt], bhf[sub * 2], bhf[sub * 2 + 1]);
                        mma16816(c, ah[mt], blf[sub * 2], blf[sub * 2 + 1]);
                    }
                }
            }
        }
        __syncthreads();
        if (kt + 2 < ksteps) { load_stage(s, (kt + 2) * 32); CP_COMMIT; }
    }

    if (MODE == 0) {
        const int which = bn >> 9;
        bf* OH = (which == 0) ? O0h : (which == 1) ? O1h : O2h;
        bf* OL = (which == 0) ? O0l : (which == 1) ? O1l : O2l;
        const int cbase = (bn & 511) + wn * 32;
#pragma unroll
        for (int mt = 0; mt < 2; mt++) {
#pragma unroll
            for (int nt = 0; nt < 4; nt++) {
                const float* c = &acc[(mt * 4 + nt) * 4];
                int row = bm + wm * 32 + mt * 16 + (lane >> 2);
                int col = cbase + nt * 8 + (lane & 3) * 2;
                bf2 h0, l0, h1, l1;
                split2(c[0], c[1], h0, l0);
                split2(c[2], c[3], h1, l1);
                *(bf2*)&OH[(size_t)row * QD_ + col] = h0;
                *(bf2*)&OL[(size_t)row * QD_ + col] = l0;
                *(bf2*)&OH[(size_t)(row + 8) * QD_ + col] = h1;
                *(bf2*)&OL[(size_t)(row + 8) * QD_ + col] = l1;
            }
        }
    } else {
        const int cbase = bn + wn * 32;
#pragma unroll
        for (int mt = 0; mt < 2; mt++) {
#pragma unroll
            for (int nt = 0; nt < 4; nt++) {
                const float* c = &acc[(mt * 4 + nt) * 4];
                int row = bm + wm * 32 + mt * 16 + (lane >> 2);
                int col = cbase + nt * 8 + (lane & 3) * 2;
                float b0 = bias[col], b1 = bias[col + 1];
                *(float2*)&Cf[(size_t)row * QD_ + col]       = make_float2(c[0] + b0, c[1] + b1);
                *(float2*)&Cf[(size_t)(row + 8) * QD_ + col] = make_float2(c[2] + b0, c[3] + b1);
            }
        }
    }
}

// =================================================================
// Mask resize + count (popcount barrier)
// =================================================================
__global__ void resize_mask(const float* __restrict__ mask,
                            float* __restrict__ m, float* __restrict__ cnt)
{
    int i = threadIdx.x;
    int r = i >> 5, c = i & 31;
    float mv = mask[(r * 2) * 64 + c * 2];
    m[i] = mv;
    int total = __syncthreads_count(mv > 0.5f);
    if (i == 0) cnt[0] = (float)total;
}

// =================================================================
// AdaIN stats phase 1: partial sums (256 blocks, bf2 channel pairs)
// =================================================================
__global__ __launch_bounds__(256) void adain_partial(
    const bf* __restrict__ khi, const bf* __restrict__ klo,
    const bf* __restrict__ vhi, const bf* __restrict__ vlo,
    const float* __restrict__ m, float* __restrict__ padain)
{
    const int tensor = blockIdx.x >> 7;
    const int cg = (blockIdx.x >> 5) & 3;
    const int rg = blockIdx.x & 31;
    const bf* Th = tensor ? vhi : khi;
    const bf* Tl = tensor ? vlo : klo;
    const int tch = threadIdx.x & 63;
    const int ch = cg * 128 + tch * 2;
    const int rp = threadIdx.x >> 6;
    const int row0 = rg * 32;

    float rs0 = 0.f, rss0 = 0.f, fs0 = 0.f, fss0 = 0.f;
    float rs1 = 0.f, rss1 = 0.f, fs1 = 0.f, fss1 = 0.f;
#pragma unroll
    for (int r = rp; r < 32; r += 4) {
        int row = row0 + r;
        bf2 rh = *(const bf2*)&Th[(size_t)row * QD_ + ch];
        bf2 rl = *(const bf2*)&Tl[(size_t)row * QD_ + ch];
        bf2 fh = *(const bf2*)&Th[(size_t)(N_ + row) * QD_ + ch];
        bf2 fl = *(const bf2*)&Tl[(size_t)(N_ + row) * QD_ + ch];
        float mv = m[row];
        float rv0 = __bfloat162float(rh.x) + __bfloat162float(rl.x);
        float rv1 = __bfloat162float(rh.y) + __bfloat162float(rl.y);
        float fv0 = __bfloat162float(fh.x) + __bfloat162float(fl.x);
        float fv1 = __bfloat162float(fh.y) + __bfloat162float(fl.y);
        rs0 += rv0; rss0 += rv0 * rv0;
        rs1 += rv1; rss1 += rv1 * rv1;
        fs0 += mv * fv0; fss0 += mv * fv0 * fv0;
        fs1 += mv * fv1; fss1 += mv * fv1 * fv1;
    }
    __shared__ float4 redA[256], redB[256];
    redA[threadIdx.x] = make_float4(rs0, rss0, fs0, fss0);
    redB[threadIdx.x] = make_float4(rs1, rss1, fs1, fss1);
    __syncthreads();
    if (rp == 0) {
        float4 a0 = redA[tch], a1 = redA[tch + 64], a2 = redA[tch + 128], a3 = redA[tch + 192];
        float4 b0 = redB[tch], b1 = redB[tch + 64], b2 = redB[tch + 128], b3 = redB[tch + 192];
        float4 oA = make_float4(a0.x + a1.x + a2.x + a3.x, a0.y + a1.y + a2.y + a3.y,
                                a0.z + a1.z + a2.z + a3.z, a0.w + a1.w + a2.w + a3.w);
        float4 oB = make_float4(b0.x + b1.x + b2.x + b3.x, b0.y + b1.y + b2.y + b3.y,
                                b0.z + b1.z + b2.z + b3.z, b0.w + b1.w + b2.w + b3.w);
        *(float4*)&padain[(((size_t)tensor * QD_ + ch)     * 32 + rg) * 4] = oA;
        *(float4*)&padain[(((size_t)tensor * QD_ + ch + 1) * 32 + rg) * 4] = oB;
    }
}

// =================================================================
// AdaIN stats phase 2: finalize scale/shift.  grid 8 x 128 thr.
// =================================================================
__global__ __launch_bounds__(128) void adain_final(
    const float* __restrict__ padain, const float* __restrict__ cntp,
    float* __restrict__ scaleArr, float* __restrict__ shiftArr)
{
    int i = blockIdx.x * 128 + threadIdx.x;
    float R = 0.f, RS = 0.f, F = 0.f, FS = 0.f;
#pragma unroll
    for (int rg = 0; rg < 32; rg++) {
        float4 p = *(const float4*)&padain[((size_t)i * 32 + rg) * 4];
        R += p.x; RS += p.y; F += p.z; FS += p.w;
    }
    float cnt = cntp[0];
    float ref_mean = R * (1.0f / N_);
    float ref_var  = (RS - (float)N_ * ref_mean * ref_mean) * (1.0f / (N_ - 1));
    float ref_std  = sqrtf(fmaxf(ref_var, 0.f));
    float f_mean   = F / cnt;
    float f_var    = (FS - cnt * f_mean * f_mean) / (cnt - 1.0f);
    float f_std    = sqrtf(fmaxf(f_var, 0.f));
    float sc = ref_std / f_std;
    scaleArr[i] = sc;
    shiftArr[i] = ref_mean - f_mean * sc;
}

// =================================================================
// AdaIN apply in-place on bf16 hi/lo (masked batch-1 rows)
// =================================================================
__global__ __launch_bounds__(256) void adain_apply2(
    bf* __restrict__ khi, bf* __restrict__ klo,
    bf* __restrict__ vhi, bf* __restrict__ vlo,
    const float* __restrict__ m,
    const float* __restrict__ scaleArr, const float* __restrict__ shiftArr)
{
    const int row = blockIdx.x & 1023;
    const int tensor = blockIdx.x >> 10;
    if (m[row] < 0.5f) return;
    bf* Th = tensor ? vhi : khi;
    bf* Tl = tensor ? vlo : klo;
    const int ch = threadIdx.x * 2;
    const size_t off = (size_t)(N_ + row) * QD_ + ch;
    bf2 h = *(bf2*)&Th[off];
    bf2 l = *(bf2*)&Tl[off];
    float v0 = __bfloat162float(h.x) + __bfloat162float(l.x);
    float v1 = __bfloat162float(h.y) + __bfloat162float(l.y);
    const float2 sc = *(const float2*)&scaleArr[tensor * QD_ + ch];
    const float2 sh = *(const float2*)&shiftArr[tensor * QD_ + ch];
    v0 = fmaf(v0, sc.x, sh.x);
    v1 = fmaf(v1, sc.y, sh.y);
    bf2 nh, nl;
    split2(v0, v1, nh, nl);
    *(bf2*)&Th[off] = nh;
    *(bf2*)&Tl[off] = nl;
}

// =================================================================
// Flash attention via mma.sync, no-max softmax.
// QK 1-term: s = qh·kh.  PV 3-term (vlo kept).
// grid (8 qtiles, 16 bh, 4 kvsplit of 8 tiles); b==0 z>=2 exact skip.
// smem 73728 -> 3 CTAs/SM.
// =================================================================
#define AQH 0
#define ATS(s) (18432 + (s) * 27648)
#define ATTN_SMEM 73728

__global__ __launch_bounds__(256, 3) void attn_mma(
    const bf* __restrict__ qhi,
    const bf* __restrict__ khi,
    const bf* __restrict__ vhi, const bf* __restrict__ vlo,
    const float* __restrict__ m,
    float* __restrict__ part, float* __restrict__ lsum)
{
    extern __shared__ __align__(16) char sma[];
    const uint32_t sb = smem_u32(sma);
    const int tid = threadIdx.x, wid = tid >> 5, lane = tid & 31;
    const int bh = blockIdx.y, b = bh >> 3, h = bh & 7;
    const int z = blockIdx.z;
    if (b == 0 && z >= 2) return;   // duplicate-key half: exact skip
    const int q0 = blockIdx.x * 128;
    const int grp = lane >> 3, lr = lane & 7;

    // ---- Q tile (hi only, 128 rows) ----
#pragma unroll
    for (int i = 0; i < 4; i++) {
        int c = tid + i * 256;
        int r = c >> 3, col = c & 7;
        const bf* src = qhi + (size_t)(b * N_ + q0 + r) * QD_ + h * DH_ + col * 8;
        cp16(sb + AQH + r * 144 + col * 16, src);
    }

    auto load_tile = [&](int s, int tileIdx) {
        int j0 = tileIdx * 64;
        int grow = (j0 < N_) ? (b * N_ + j0) : (j0 - N_);
        uint32_t tb = sb + ATS(s);
#pragma unroll
        for (int i = 0; i < 6; i++) {
            int c = tid + i * 256;
            int mt = c >> 9, r = (c >> 3) & 63, col = c & 7;
            const bf* srcb = (mt == 0) ? khi : (mt == 1) ? vhi : vlo;
            cp16(tb + mt * 9216 + r * 144 + col * 16,
                 srcb + (size_t)(grow + r) * QD_ + h * DH_ + col * 8);
        }
    };

    load_tile(0, z * 8);     CP_COMMIT;
    load_tile(1, z * 8 + 1); CP_COMMIT;
    CP_WAIT1;
    __syncthreads();

    // ---- Q fragments ----
    uint32_t qh[16];
    {
        uint32_t base = sb + AQH + (wid * 16 + (lane & 15)) * 144 + (lane >> 4) * 16;
#pragma unroll
        for (int k16 = 0; k16 < 4; k16++) ldsm4(&qh[k16 * 4], base + k16 * 32);
    }

    const int r4 = lane >> 2;
    const int qrow = q0 + wid * 16 + r4;
    float flag0 = 1.f, flag1 = 1.f;
    if (b == 1 && z >= 2) {
        flag0 = (m[qrow]     < 0.5f) ? 0.f : 1.f;
        flag1 = (m[qrow + 8] < 0.5f) ? 0.f : 1.f;
    }

    float o[32];
#pragma unroll
    for (int i = 0; i < 32; i++) o[i] = 0.f;
    float l0 = 0.f, l1 = 0.f;

    const int rowKb = ((grp >> 1) << 3) + lr;
    const int colK  = (grp & 1) * 16;
    const int rowVb = ((grp & 1) << 3) + lr;
    const int colV  = (grp >> 1) * 16;

    for (int kt = 0; kt < 8; kt++) {
        const int s = kt & 1;
        if (kt > 0) {
            if (kt == 7) { CP_WAIT0; } else { CP_WAIT1; }
            __syncthreads();
        }
        const uint32_t khb = sb + ATS(s);
        const uint32_t vhb = khb + 9216;
        const uint32_t vlb = khb + 18432;

#pragma unroll
        for (int kk = 0; kk < 4; kk++) {
            float s0[4] = {0.f, 0.f, 0.f, 0.f};
            float s1[4] = {0.f, 0.f, 0.f, 0.f};
            const uint32_t kro = (kk * 16 + rowKb) * 144 + colK;
#pragma unroll
            for (int k16 = 0; k16 < 4; k16++) {
                uint32_t bhf[4];
                ldsm4(bhf, khb + kro + k16 * 32);
                mma16816(s0, &qh[k16 * 4], bhf[0], bhf[1]);
                mma16816(s1, &qh[k16 * 4], bhf[2], bhf[3]);
            }
            s0[0] = __expf(s0[0] * SCALE_) * flag0;
            s0[1] = __expf(s0[1] * SCALE_) * flag0;
            s0[2] = __expf(s0[2] * SCALE_) * flag1;
            s0[3] = __expf(s0[3] * SCALE_) * flag1;
            s1[0] = __expf(s1[0] * SCALE_) * flag0;
            s1[1] = __expf(s1[1] * SCALE_) * flag0;
            s1[2] = __expf(s1[2] * SCALE_) * flag1;
            s1[3] = __expf(s1[3] * SCALE_) * flag1;
            l0 += s0[0] + s0[1] + s1[0] + s1[1];
            l1 += s0[2] + s0[3] + s1[2] + s1[3];

            uint32_t ph[4], pl[4];
            ph[0] = pkbf(s0[0], s0[1]);
            pl[0] = pkbf(s0[0] - lo16f(ph[0]), s0[1] - hi16f(ph[0]));
            ph[1] = pkbf(s0[2], s0[3]);
            pl[1] = pkbf(s0[2] - lo16f(ph[1]), s0[3] - hi16f(ph[1]));
            ph[2] = pkbf(s1[0], s1[1]);
            pl[2] = pkbf(s1[0] - lo16f(ph[2]), s1[1] - hi16f(ph[2]));
            ph[3] = pkbf(s1[2], s1[3]);
            pl[3] = pkbf(s1[2] - lo16f(ph[3]), s1[3] - hi16f(ph[3]));

            const uint32_t vro = (kk * 16 + rowVb) * 144 + colV;
#pragma unroll
            for (int dp = 0; dp < 4; dp++) {
                uint32_t vhf[4], vlf[4];
                ldsm4t(vhf, vhb + vro + dp * 32);
                ldsm4t(vlf, vlb + vro + dp * 32);
                mma16816(&o[dp * 8],     ph, vhf[0], vhf[1]);
                mma16816(&o[dp * 8 + 4], ph, vhf[2], vhf[3]);
                mma16816(&o[dp * 8],     pl, vhf[0], vhf[1]);
                mma16816(&o[dp * 8 + 4], pl, vhf[2], vhf[3]);
                mma16816(&o[dp * 8],     ph, vlf[0], vlf[1]);
                mma16816(&o[dp * 8 + 4], ph, vlf[2], vlf[3]);
            }
        }
        __syncthreads();
        if (kt + 2 < 8) { load_tile(s, z * 8 + kt + 2); CP_COMMIT; }
    }

    // ---- epilogue ----
    l0 += __shfl_xor_sync(0xffffffffu, l0, 1);
    l0 += __shfl_xor_sync(0xffffffffu, l0, 2);
    l1 += __shfl_xor_sync(0xffffffffu, l1, 1);
    l1 += __shfl_xor_sync(0xffffffffu, l1, 2);

    float* pd = part + (size_t)(z * 16 + bh) * N_ * DH_;
#pragma unroll
    for (int nt = 0; nt < 8; nt++) {
        int col = nt * 8 + (lane & 3) * 2;
        *(float2*)&pd[(size_t)qrow * DH_ + col]       = make_float2(o[nt * 4 + 0], o[nt * 4 + 1]);
        *(float2*)&pd[(size_t)(qrow + 8) * DH_ + col] = make_float2(o[nt * 4 + 2], o[nt * 4 + 3]);
    }
    if ((lane & 3) == 0) {
        lsum[(z * 16 + bh) * N_ + qrow]     = l0;
        lsum[(z * 16 + bh) * N_ + qrow + 8] = l1;
    }
}

// =================================================================
// Combine kv-split partials -> aohi/aolo (batch 0 uses z=0,1 only)
// =================================================================
__global__ __launch_bounds__(128) void attn_reduce(
    const float* __restrict__ part, const float* __restrict__ lsum,
    bf* __restrict__ aoh, bf* __restrict__ aol)
{
    int row = blockIdx.x * 128 + threadIdx.x;
    int bh = row >> 10, qi = row & 1023;
    int b = bh >> 3, h = bh & 7;
    const int zmax = (b == 0) ? 2 : KVSPLIT;

    float l = 0.f;
    for (int z = 0; z < zmax; z++) l += lsum[(z * 16 + bh) * N_ + qi];
    float inv = 1.0f / l;

    size_t dbase = (size_t)(b * N_ + qi) * QD_ + h * DH_;
#pragma unroll
    for (int d4 = 0; d4 < 16; d4++) {
        float4 acc = make_float4(0.f, 0.f, 0.f, 0.f);
        for (int z = 0; z < zmax; z++) {
            const float4 p4 = ((const float4*)(part +
                ((size_t)(z * 16 + bh) * N_ + qi) * DH_))[d4];
            acc.x += p4.x; acc.y += p4.y; acc.z += p4.z; acc.w += p4.w;
        }
        bf2 h0, l0, h1, l1;
        split2(acc.x * inv, acc.y * inv, h0, l0);
        split2(acc.z * inv, acc.w * inv, h1, l1);
        *(bf2*)&aoh[dbase + d4 * 4]     = h0;
        *(bf2*)&aol[dbase + d4 * 4]     = l0;
        *(bf2*)&aoh[dbase + d4 * 4 + 2] = h1;
        *(bf2*)&aol[dbase + d4 * 4 + 2] = l1;
    }
}

// =================================================================
extern "C" void kernel_launch(void* const* d_in, const int* in_sizes, int n_in,
                              void* d_out, int out_size)
{
    const float* x    = (const float*)d_in[0];
    const float* mask = (const float*)d_in[1];
    const float* Wq   = (const float*)d_in[2];
    const float* Wk   = (const float*)d_in[3];
    const float* Wv   = (const float*)d_in[4];
    const float* Wo   = (const float*)d_in[5];
    const float* bo   = (const float*)d_in[6];

    float *m, *cnt, *sc, *sh, *prt, *lsm, *pad;
    bf *xhi, *xlo, *whi, *wlo, *qhi, *qlo, *khi, *klo, *vhi, *vlo, *aohi, *aolo;
    cudaGetSymbolAddress((void**)&m,    g_m);
    cudaGetSymbolAddress((void**)&cnt,  g_cnt);
    cudaGetSymbolAddress((void**)&sc,   g_scale);
    cudaGetSymbolAddress((void**)&sh,   g_shift);
    cudaGetSymbolAddress((void**)&prt,  g_part);
    cudaGetSymbolAddress((void**)&lsm,  g_lsum);
    cudaGetSymbolAddress((void**)&pad,  g_padain);
    cudaGetSymbolAddress((void**)&xhi,  g_xhi);
    cudaGetSymbolAddress((void**)&xlo,  g_xlo);
    cudaGetSymbolAddress((void**)&whi,  g_whi);
    cudaGetSymbolAddress((void**)&wlo,  g_wlo);
    cudaGetSymbolAddress((void**)&qhi,  g_qhi);
    cudaGetSymbolAddress((void**)&qlo,  g_qlo);
    cudaGetSymbolAddress((void**)&khi,  g_khi);
    cudaGetSymbolAddress((void**)&klo,  g_klo);
    cudaGetSymbolAddress((void**)&vhi,  g_vhi);
    cudaGetSymbolAddress((void**)&vlo,  g_vlo);
    cudaGetSymbolAddress((void**)&aohi, g_aohi);
    cudaGetSymbolAddress((void**)&aolo, g_aolo);

    cudaFuncSetAttribute(gemm_mma<0>, cudaFuncAttributeMaxDynamicSharedMemorySize, GEMM_SMEM);
    cudaFuncSetAttribute(gemm_mma<1>, cudaFuncAttributeMaxDynamicSharedMemorySize, GEMM_SMEM);
    cudaFuncSetAttribute(attn_mma, cudaFuncAttributeMaxDynamicSharedMemorySize, ATTN_SMEM);

    const int M = B_ * N_;        // 2048
    const int WS = QD_ * QD_;     // 262144

    cvt_all<<<2048, 256>>>((const float4*)x,
                           (const float4*)Wq, (const float4*)Wk,
                           (const float4*)Wv, (const float4*)Wo,
                           (bf2*)xhi, (bf2*)xlo, (bf2*)whi, (bf2*)wlo);
    resize_mask<<<1, 1024>>>(mask, m, cnt);

    // fused QKV projection (N = 1536), 128x64 tiles, BK=32, 3 CTAs/SM
    gemm_mma<0><<<dim3(24, 16), 256, GEMM_SMEM>>>(
        xhi, xlo, whi, wlo, nullptr, nullptr,
        qhi, qlo, khi, klo, vhi, vlo, M, QD_);

    adain_partial<<<256, 256>>>(khi, klo, vhi, vlo, m, pad);
    adain_final<<<8, 128>>>(pad, cnt, sc, sh);
    adain_apply2<<<2048, 256>>>(khi, klo, vhi, vlo, m, sc, sh);

    attn_mma<<<dim3(8, 16, KVSPLIT), 256, ATTN_SMEM>>>(qhi, khi, vhi, vlo, m, prt, lsm);
    attn_reduce<<<128, 128>>>(prt, lsm, aohi, aolo);

    gemm_mma<1><<<dim3(8, 16), 256, GEMM_SMEM>>>(
        aohi, aolo, whi + 3 * WS, wlo + 3 * WS, bo, (float*)d_out,
        nullptr, nullptr, nullptr, nullptr, nullptr, nullptr, M, QD_);
}

// round 13
// speedup vs baseline: 1.0534x; 1.0534x over previous
#include <cuda_runtime.h>
#include <cuda_bf16.h>
#include <math.h>
#include <stdint.h>

// Problem constants
#define B_    2
#define N_    1024
#define QD_   512
#define H_    8
#define DH_   64
#define SCALE_ 0.125f   // DH^-0.5
#define KVSPLIT 4

// ---------------- PTX helpers ----------------
__device__ __forceinline__ uint32_t smem_u32(const void* p) {
    uint32_t a;
    asm("{ .reg .u64 t; cvta.to.shared.u64 t, %1; cvt.u32.u64 %0, t; }" : "=r"(a) : "l"(p));
    return a;
}
__device__ __forceinline__ void cp16(uint32_t dst, const void* src) {
    asm volatile("cp.async.cg.shared.global [%0], [%1], 16;" :: "r"(dst), "l"(src) : "memory");
}
#define CP_COMMIT asm volatile("cp.async.commit_group;" ::: "memory")
#define CP_WAIT1  asm volatile("cp.async.wait_group 1;" ::: "memory")
#define CP_WAIT0  asm volatile("cp.async.wait_group 0;" ::: "memory")

__device__ __forceinline__ void ldsm4(uint32_t* r, uint32_t a) {
    asm volatile("ldmatrix.sync.aligned.m8n8.x4.shared.b16 {%0,%1,%2,%3}, [%4];"
                 : "=r"(r[0]), "=r"(r[1]), "=r"(r[2]), "=r"(r[3]) : "r"(a));
}
__device__ __forceinline__ void ldsm4t(uint32_t* r, uint32_t a) {
    asm volatile("ldmatrix.sync.aligned.m8n8.x4.trans.shared.b16 {%0,%1,%2,%3}, [%4];"
                 : "=r"(r[0]), "=r"(r[1]), "=r"(r[2]), "=r"(r[3]) : "r"(a));
}
__device__ __forceinline__ void mma16816(float* c, const uint32_t* a, uint32_t b0, uint32_t b1) {
    asm volatile(
        "mma.sync.aligned.m16n8k16.row.col.f32.bf16.bf16.f32 "
        "{%0,%1,%2,%3}, {%4,%5,%6,%7}, {%8,%9}, {%0,%1,%2,%3};"
        : "+f"(c[0]), "+f"(c[1]), "+f"(c[2]), "+f"(c[3])
        : "r"(a[0]), "r"(a[1]), "r"(a[2]), "r"(a[3]), "r"(b0), "r"(b1));
}
__device__ __forceinline__ uint32_t pkbf(float lo, float hi) {
    uint32_t r;
    asm("cvt.rn.satfinite.bf16x2.f32 %0, %1, %2;" : "=r"(r) : "f"(hi), "f"(lo));
    return r;
}
__device__ __forceinline__ float lo16f(uint32_t u) { return __uint_as_float(u << 16); }
__device__ __forceinline__ float hi16f(uint32_t u) { return __uint_as_float(u & 0xffff0000u); }

typedef __nv_bfloat16 bf;
typedef __nv_bfloat162 bf2;

// ---------------- scratch ----------------
__device__ float g_m [N_];
__device__ float g_cnt[1];
__device__ float g_scale[2*QD_];
__device__ float g_shift[2*QD_];
__device__ float g_padain[2*QD_*32*4];    // [tensor][ch][rowgrp(32)][4]
__device__ bf g_xhi[B_*N_*QD_], g_xlo[B_*N_*QD_];
__device__ bf g_whi[4][QD_*QD_], g_wlo[4][QD_*QD_];
__device__ bf g_qhi[B_*N_*QD_], g_qlo[B_*N_*QD_];
__device__ bf g_khi[B_*N_*QD_], g_klo[B_*N_*QD_];
__device__ bf g_vhi[B_*N_*QD_], g_vlo[B_*N_*QD_];
__device__ bf g_aohi[B_*N_*QD_], g_aolo[B_*N_*QD_];
__device__ float g_part[KVSPLIT*16*N_*DH_];
__device__ float g_lsum[KVSPLIT*16*N_];

// =================================================================
// fp32 -> bf16 hi/lo split helpers
// =================================================================
__device__ __forceinline__ void split2(float a, float b, bf2& h2, bf2& l2) {
    bf h0 = __float2bfloat16(a), h1 = __float2bfloat16(b);
    h2.x = h0; h2.y = h1;
    l2.x = __float2bfloat16(a - __bfloat162float(h0));
    l2.y = __float2bfloat16(b - __bfloat162float(h1));
}

// Fused conversion + mask kernel:
// blocks [0, 2048): x (262144 f4) then W0..W3 (4 x 65536 f4)
// block 2048: mask resize (64x64 -> 32x32 nearest) + count
__global__ __launch_bounds__(256) void cvt_all(
    const float4* __restrict__ x,
    const float4* __restrict__ w0, const float4* __restrict__ w1,
    const float4* __restrict__ w2, const float4* __restrict__ w3,
    bf2* __restrict__ xhi, bf2* __restrict__ xlo,
    bf2* __restrict__ whi, bf2* __restrict__ wlo,
    const float* __restrict__ mask, float* __restrict__ m, float* __restrict__ cnt)
{
    if (blockIdx.x == 2048) {
        // mask block: 256 threads x 4 elements
        int t = threadIdx.x;
        float s = 0.f;
#pragma unroll
        for (int j = 0; j < 4; j++) {
            int i = t * 4 + j;
            int r = i >> 5, c = i & 31;
            float mv = mask[(r * 2) * 64 + c * 2];
            m[i] = mv;
            s += mv;
        }
        __shared__ float red[256];
        red[t] = s;
        __syncthreads();
        for (int st = 128; st > 0; st >>= 1) {
            if (t < st) red[t] += red[t + st];
            __syncthreads();
        }
        if (t == 0) cnt[0] = red[0];
        return;
    }

    int i = blockIdx.x * 256 + threadIdx.x;      // [0, 524288)
    const float4* src;
    bf2 *hi, *lo;
    size_t o;
    if (i < 262144) {
        src = x + i; hi = xhi; lo = xlo; o = (size_t)i * 2;
    } else {
        int j = i - 262144;
        int t = j >> 16, jj = j & 65535;
        src = ((t == 0) ? w0 : (t == 1) ? w1 : (t == 2) ? w2 : w3) + jj;
        hi = whi; lo = wlo; o = (size_t)j * 2;
    }
    float4 v = *src;
    bf2 h0, l0, h1, l1;
    split2(v.x, v.y, h0, l0);
    split2(v.z, v.w, h1, l1);
    hi[o] = h0; hi[o+1] = h1;
    lo[o] = l0; lo[o+1] = l1;
}

// =================================================================
// mma.sync GEMM, tile 128x64, BK=64, 2-stage cp.async, split-bf16.
// MODE 0: fused QKV -> bf16 hi/lo; MODE 1: fp32 + bias.
// =================================================================
#define S_AH(s) ((s)*55296 + 0)
#define S_AL(s) ((s)*55296 + 18432)
#define S_BH(s) ((s)*55296 + 36864)
#define S_BL(s) ((s)*55296 + 46080)
#define GEMM_SMEM 110592

template<int MODE>
__global__ __launch_bounds__(256, 2) void gemm_mma(
    const bf* __restrict__ Ahi, const bf* __restrict__ Alo,
    const bf* __restrict__ Bhi, const bf* __restrict__ Blo,
    const float* __restrict__ bias, float* __restrict__ Cf,
    bf* __restrict__ O0h, bf* __restrict__ O0l,
    bf* __restrict__ O1h, bf* __restrict__ O1l,
    bf* __restrict__ O2h, bf* __restrict__ O2l,
    int M, int K)
{
    extern __shared__ __align__(16) char sg[];
    const uint32_t sb = smem_u32(sg);
    const int tid = threadIdx.x;
    const int warp = tid >> 5, lane = tid & 31;
    const int wm = warp & 3, wn = warp >> 2;
    const int bm = blockIdx.y * 128, bn = blockIdx.x * 64;
    const int grp = lane >> 3, lr = lane & 7;

    auto load_stage = [&](int s, int k0) {
#pragma unroll
        for (int i = 0; i < 4; i++) {           // A hi
            int c = tid + i * 256;
            int r = c >> 3, col = c & 7;
            cp16(sb + S_AH(s) + r * 144 + col * 16,
                 Ahi + (size_t)(bm + r) * K + k0 + col * 8);
        }
#pragma unroll
        for (int i = 0; i < 4; i++) {           // A lo
            int c = tid + i * 256;
            int r = c >> 3, col = c & 7;
            cp16(sb + S_AL(s) + r * 144 + col * 16,
                 Alo + (size_t)(bm + r) * K + k0 + col * 8);
        }
#pragma unroll
        for (int i = 0; i < 2; i++) {           // B hi
            int c = tid + i * 256;
            int r = c >> 3, col = c & 7;
            cp16(sb + S_BH(s) + r * 144 + col * 16,
                 Bhi + (size_t)(bn + r) * K + k0 + col * 8);
        }
#pragma unroll
        for (int i = 0; i < 2; i++) {           // B lo
            int c = tid + i * 256;
            int r = c >> 3, col = c & 7;
            cp16(sb + S_BL(s) + r * 144 + col * 16,
                 Blo + (size_t)(bn + r) * K + k0 + col * 8);
        }
    };

    float acc[32];
#pragma unroll
    for (int i = 0; i < 32; i++) acc[i] = 0.f;

    const int ksteps = K >> 6;    // 8 for K=512
    load_stage(0, 0);  CP_COMMIT;
    load_stage(1, 64); CP_COMMIT;

    const uint32_t aaddr = (wm * 32 + (lane & 15)) * 144 + (lane >> 4) * 16;
    const int rowB = wn * 32 + ((grp >> 1) << 3) + lr;
    const int colB = (grp & 1) * 16;

    for (int kt = 0; kt < ksteps; kt++) {
        if (kt == ksteps - 1) { CP_WAIT0; } else { CP_WAIT1; }
        __syncthreads();
        const int s = kt & 1;
        const uint32_t ahb = sb + S_AH(s), alb = sb + S_AL(s);
        const uint32_t bhb = sb + S_BH(s), blb = sb + S_BL(s);

#pragma unroll
        for (int kb = 0; kb < 4; kb++) {
            uint32_t ah[2][4], al[2][4];
#pragma unroll
            for (int mt = 0; mt < 2; mt++) {
                ldsm4(ah[mt], ahb + aaddr + mt * 16 * 144 + kb * 32);
                ldsm4(al[mt], alb + aaddr + mt * 16 * 144 + kb * 32);
            }
#pragma unroll
            for (int p = 0; p < 2; p++) {
                uint32_t bhf[4], blf[4];
                ldsm4(bhf, bhb + (rowB + p * 16) * 144 + kb * 32 + colB);
                ldsm4(blf, blb + (rowB + p * 16) * 144 + kb * 32 + colB);
#pragma unroll
                for (int mt = 0; mt < 2; mt++) {
#pragma unroll
                    for (int sub = 0; sub < 2; sub++) {
                        float* c = &acc[(mt * 4 + p * 2 + sub) * 4];
                        mma16816(c, ah[mt], bhf[sub * 2], bhf[sub * 2 + 1]);
                        mma16816(c, al[mt], bhf[sub * 2], bhf[sub * 2 + 1]);
                        mma16816(c, ah[mt], blf[sub * 2], blf[sub * 2 + 1]);
                    }
                }
            }
        }
        __syncthreads();
        if (kt + 2 < ksteps) { load_stage(s, (kt + 2) * 64); CP_COMMIT; }
    }

    if (MODE == 0) {
        const int which = bn >> 9;
        bf* OH = (which == 0) ? O0h : (which == 1) ? O1h : O2h;
        bf* OL = (which == 0) ? O0l : (which == 1) ? O1l : O2l;
        const int cbase = (bn & 511) + wn * 32;
#pragma unroll
        for (int mt = 0; mt < 2; mt++) {
#pragma unroll
            for (int nt = 0; nt < 4; nt++) {
                const float* c = &acc[(mt * 4 + nt) * 4];
                int row = bm + wm * 32 + mt * 16 + (lane >> 2);
                int col = cbase + nt * 8 + (lane & 3) * 2;
                bf2 h0, l0, h1, l1;
                split2(c[0], c[1], h0, l0);
                split2(c[2], c[3], h1, l1);
                *(bf2*)&OH[(size_t)row * QD_ + col] = h0;
                *(bf2*)&OL[(size_t)row * QD_ + col] = l0;
                *(bf2*)&OH[(size_t)(row + 8) * QD_ + col] = h1;
                *(bf2*)&OL[(size_t)(row + 8) * QD_ + col] = l1;
            }
        }
    } else {
        const int cbase = bn + wn * 32;
#pragma unroll
        for (int mt = 0; mt < 2; mt++) {
#pragma unroll
            for (int nt = 0; nt < 4; nt++) {
                const float* c = &acc[(mt * 4 + nt) * 4];
                int row = bm + wm * 32 + mt * 16 + (lane >> 2);
                int col = cbase + nt * 8 + (lane & 3) * 2;
                float b0 = bias[col], b1 = bias[col + 1];
                *(float2*)&Cf[(size_t)row * QD_ + col]       = make_float2(c[0] + b0, c[1] + b1);
                *(float2*)&Cf[(size_t)(row + 8) * QD_ + col] = make_float2(c[2] + b0, c[3] + b1);
            }
        }
    }
}

// =================================================================
// AdaIN stats phase 1: partial sums (256 blocks, bf2 channel pairs)
// =================================================================
__global__ __launch_bounds__(256) void adain_partial(
    const bf* __restrict__ khi, const bf* __restrict__ klo,
    const bf* __restrict__ vhi, const bf* __restrict__ vlo,
    const float* __restrict__ m, float* __restrict__ padain)
{
    const int tensor = blockIdx.x >> 7;
    const int cg = (blockIdx.x >> 5) & 3;
    const int rg = blockIdx.x & 31;
    const bf* Th = tensor ? vhi : khi;
    const bf* Tl = tensor ? vlo : klo;
    const int tch = threadIdx.x & 63;
    const int ch = cg * 128 + tch * 2;
    const int rp = threadIdx.x >> 6;
    const int row0 = rg * 32;

    float rs0 = 0.f, rss0 = 0.f, fs0 = 0.f, fss0 = 0.f;
    float rs1 = 0.f, rss1 = 0.f, fs1 = 0.f, fss1 = 0.f;
#pragma unroll
    for (int r = rp; r < 32; r += 4) {
        int row = row0 + r;
        bf2 rh = *(const bf2*)&Th[(size_t)row * QD_ + ch];
        bf2 rl = *(const bf2*)&Tl[(size_t)row * QD_ + ch];
        bf2 fh = *(const bf2*)&Th[(size_t)(N_ + row) * QD_ + ch];
        bf2 fl = *(const bf2*)&Tl[(size_t)(N_ + row) * QD_ + ch];
        float mv = m[row];
        float rv0 = __bfloat162float(rh.x) + __bfloat162float(rl.x);
        float rv1 = __bfloat162float(rh.y) + __bfloat162float(rl.y);
        float fv0 = __bfloat162float(fh.x) + __bfloat162float(fl.x);
        float fv1 = __bfloat162float(fh.y) + __bfloat162float(fl.y);
        rs0 += rv0; rss0 += rv0 * rv0;
        rs1 += rv1; rss1 += rv1 * rv1;
        fs0 += mv * fv0; fss0 += mv * fv0 * fv0;
        fs1 += mv * fv1; fss1 += mv * fv1 * fv1;
    }
    __shared__ float4 redA[256], redB[256];
    redA[threadIdx.x] = make_float4(rs0, rss0, fs0, fss0);
    redB[threadIdx.x] = make_float4(rs1, rss1, fs1, fss1);
    __syncthreads();
    if (rp == 0) {
        float4 a0 = redA[tch], a1 = redA[tch + 64], a2 = redA[tch + 128], a3 = redA[tch + 192];
        float4 b0 = redB[tch], b1 = redB[tch + 64], b2 = redB[tch + 128], b3 = redB[tch + 192];
        float4 oA = make_float4(a0.x + a1.x + a2.x + a3.x, a0.y + a1.y + a2.y + a3.y,
                                a0.z + a1.z + a2.z + a3.z, a0.w + a1.w + a2.w + a3.w);
        float4 oB = make_float4(b0.x + b1.x + b2.x + b3.x, b0.y + b1.y + b2.y + b3.y,
                                b0.z + b1.z + b2.z + b3.z, b0.w + b1.w + b2.w + b3.w);
        *(float4*)&padain[(((size_t)tensor * QD_ + ch)     * 32 + rg) * 4] = oA;
        *(float4*)&padain[(((size_t)tensor * QD_ + ch + 1) * 32 + rg) * 4] = oB;
    }
}

// =================================================================
// AdaIN stats phase 2: finalize scale/shift.  grid 8 x 128 thr.
// =================================================================
__global__ __launch_bounds__(128) void adain_final(
    const float* __restrict__ padain, const float* __restrict__ cntp,
    float* __restrict__ scaleArr, float* __restrict__ shiftArr)
{
    int i = blockIdx.x * 128 + threadIdx.x;
    float R = 0.f, RS = 0.f, F = 0.f, FS = 0.f;
#pragma unroll
    for (int rg = 0; rg < 32; rg++) {
        float4 p = *(const float4*)&padain[((size_t)i * 32 + rg) * 4];
        R += p.x; RS += p.y; F += p.z; FS += p.w;
    }
    float cnt = cntp[0];
    float ref_mean = R * (1.0f / N_);
    float ref_var  = (RS - (float)N_ * ref_mean * ref_mean) * (1.0f / (N_ - 1));
    float ref_std  = sqrtf(fmaxf(ref_var, 0.f));
    float f_mean   = F / cnt;
    float f_var    = (FS - cnt * f_mean * f_mean) / (cnt - 1.0f);
    float f_std    = sqrtf(fmaxf(f_var, 0.f));
    float sc = ref_std / f_std;
    scaleArr[i] = sc;
    shiftArr[i] = ref_mean - f_mean * sc;
}

// =================================================================
// AdaIN apply in-place on bf16 hi/lo (masked batch-1 rows)
// =================================================================
__global__ __launch_bounds__(256) void adain_apply2(
    bf* __restrict__ khi, bf* __restrict__ klo,
    bf* __restrict__ vhi, bf* __restrict__ vlo,
    const float* __restrict__ m,
    const float* __restrict__ scaleArr, const float* __restrict__ shiftArr)
{
    const int row = blockIdx.x & 1023;
    const int tensor = blockIdx.x >> 10;
    if (m[row] < 0.5f) return;
    bf* Th = tensor ? vhi : khi;
    bf* Tl = tensor ? vlo : klo;
    const int ch = threadIdx.x * 2;
    const size_t off = (size_t)(N_ + row) * QD_ + ch;
    bf2 h = *(bf2*)&Th[off];
    bf2 l = *(bf2*)&Tl[off];
    float v0 = __bfloat162float(h.x) + __bfloat162float(l.x);
    float v1 = __bfloat162float(h.y) + __bfloat162float(l.y);
    const float2 sc = *(const float2*)&scaleArr[tensor * QD_ + ch];
    const float2 sh = *(const float2*)&shiftArr[tensor * QD_ + ch];
    v0 = fmaf(v0, sc.x, sh.x);
    v1 = fmaf(v1, sc.y, sh.y);
    bf2 nh, nl;
    split2(v0, v1, nh, nl);
    *(bf2*)&Th[off] = nh;
    *(bf2*)&Tl[off] = nl;
}

// =================================================================
// Flash attention via mma.sync, no-max softmax.
// QK 1-term: s = qh·kh.  PV 3-term (vlo kept).
// grid (8 qtiles, 16 bh, 4 kvsplit of 8 tiles); b==0 z>=2 exact skip.
// smem 73728 -> 3 CTAs/SM.
// =================================================================
#define AQH 0
#define ATS(s) (18432 + (s) * 27648)
#define ATTN_SMEM 73728

__global__ __launch_bounds__(256, 3) void attn_mma(
    const bf* __restrict__ qhi,
    const bf* __restrict__ khi,
    const bf* __restrict__ vhi, const bf* __restrict__ vlo,
    const float* __restrict__ m,
    float* __restrict__ part, float* __restrict__ lsum)
{
    extern __shared__ __align__(16) char sma[];
    const uint32_t sb = smem_u32(sma);
    const int tid = threadIdx.x, wid = tid >> 5, lane = tid & 31;
    const int bh = blockIdx.y, b = bh >> 3, h = bh & 7;
    const int z = blockIdx.z;
    if (b == 0 && z >= 2) return;   // duplicate-key half: exact skip
    const int q0 = blockIdx.x * 128;
    const int grp = lane >> 3, lr = lane & 7;

    // ---- Q tile (hi only, 128 rows) ----
#pragma unroll
    for (int i = 0; i < 4; i++) {
        int c = tid + i * 256;
        int r = c >> 3, col = c & 7;
        const bf* src = qhi + (size_t)(b * N_ + q0 + r) * QD_ + h * DH_ + col * 8;
        cp16(sb + AQH + r * 144 + col * 16, src);
    }

    auto load_tile = [&](int s, int tileIdx) {
        int j0 = tileIdx * 64;
        int grow = (j0 < N_) ? (b * N_ + j0) : (j0 - N_);
        uint32_t tb = sb + ATS(s);
#pragma unroll
        for (int i = 0; i < 6; i++) {
            int c = tid + i * 256;
            int mt = c >> 9, r = (c >> 3) & 63, col = c & 7;
            const bf* srcb = (mt == 0) ? khi : (mt == 1) ? vhi : vlo;
            cp16(tb + mt * 9216 + r * 144 + col * 16,
                 srcb + (size_t)(grow + r) * QD_ + h * DH_ + col * 8);
        }
    };

    load_tile(0, z * 8);     CP_COMMIT;
    load_tile(1, z * 8 + 1); CP_COMMIT;
    CP_WAIT1;
    __syncthreads();

    // ---- Q fragments ----
    uint32_t qh[16];
    {
        uint32_t base = sb + AQH + (wid * 16 + (lane & 15)) * 144 + (lane >> 4) * 16;
#pragma unroll
        for (int k16 = 0; k16 < 4; k16++) ldsm4(&qh[k16 * 4], base + k16 * 32);
    }

    const int r4 = lane >> 2;
    const int qrow = q0 + wid * 16 + r4;
    float flag0 = 1.f, flag1 = 1.f;
    if (b == 1 && z >= 2) {
        flag0 = (m[qrow]     < 0.5f) ? 0.f : 1.f;
        flag1 = (m[qrow + 8] < 0.5f) ? 0.f : 1.f;
    }

    float o[32];
#pragma unroll
    for (int i = 0; i < 32; i++) o[i] = 0.f;
    float l0 = 0.f, l1 = 0.f;

    const int rowKb = ((grp >> 1) << 3) + lr;
    const int colK  = (grp & 1) * 16;
    const int rowVb = ((grp & 1) << 3) + lr;
    const int colV  = (grp >> 1) * 16;

    for (int kt = 0; kt < 8; kt++) {
        const int s = kt & 1;
        if (kt > 0) {
            if (kt == 7) { CP_WAIT0; } else { CP_WAIT1; }
            __syncthreads();
        }
        const uint32_t khb = sb + ATS(s);
        const uint32_t vhb = khb + 9216;
        const uint32_t vlb = khb + 18432;

#pragma unroll
        for (int kk = 0; kk < 4; kk++) {
            float s0[4] = {0.f, 0.f, 0.f, 0.f};
            float s1[4] = {0.f, 0.f, 0.f, 0.f};
            const uint32_t kro = (kk * 16 + rowKb) * 144 + colK;
#pragma unroll
            for (int k16 = 0; k16 < 4; k16++) {
                uint32_t bhf[4];
                ldsm4(bhf, khb + kro + k16 * 32);
                mma16816(s0, &qh[k16 * 4], bhf[0], bhf[1]);
                mma16816(s1, &qh[k16 * 4], bhf[2], bhf[3]);
            }
            s0[0] = __expf(s0[0] * SCALE_) * flag0;
            s0[1] = __expf(s0[1] * SCALE_) * flag0;
            s0[2] = __expf(s0[2] * SCALE_) * flag1;
            s0[3] = __expf(s0[3] * SCALE_) * flag1;
            s1[0] = __expf(s1[0] * SCALE_) * flag0;
            s1[1] = __expf(s1[1] * SCALE_) * flag0;
            s1[2] = __expf(s1[2] * SCALE_) * flag1;
            s1[3] = __expf(s1[3] * SCALE_) * flag1;
            l0 += s0[0] + s0[1] + s1[0] + s1[1];
            l1 += s0[2] + s0[3] + s1[2] + s1[3];

            uint32_t ph[4], pl[4];
            ph[0] = pkbf(s0[0], s0[1]);
            pl[0] = pkbf(s0[0] - lo16f(ph[0]), s0[1] - hi16f(ph[0]));
            ph[1] = pkbf(s0[2], s0[3]);
            pl[1] = pkbf(s0[2] - lo16f(ph[1]), s0[3] - hi16f(ph[1]));
            ph[2] = pkbf(s1[0], s1[1]);
            pl[2] = pkbf(s1[0] - lo16f(ph[2]), s1[1] - hi16f(ph[2]));
            ph[3] = pkbf(s1[2], s1[3]);
            pl[3] = pkbf(s1[2] - lo16f(ph[3]), s1[3] - hi16f(ph[3]));

            const uint32_t vro = (kk * 16 + rowVb) * 144 + colV;
#pragma unroll
            for (int dp = 0; dp < 4; dp++) {
                uint32_t vhf[4], vlf[4];
                ldsm4t(vhf, vhb + vro + dp * 32);
                ldsm4t(vlf, vlb + vro + dp * 32);
                mma16816(&o[dp * 8],     ph, vhf[0], vhf[1]);
                mma16816(&o[dp * 8 + 4], ph, vhf[2], vhf[3]);
                mma16816(&o[dp * 8],     pl, vhf[0], vhf[1]);
                mma16816(&o[dp * 8 + 4], pl, vhf[2], vhf[3]);
                mma16816(&o[dp * 8],     ph, vlf[0], vlf[1]);
                mma16816(&o[dp * 8 + 4], ph, vlf[2], vlf[3]);
            }
        }
        __syncthreads();
        if (kt + 2 < 8) { load_tile(s, z * 8 + kt + 2); CP_COMMIT; }
    }

    // ---- epilogue ----
    l0 += __shfl_xor_sync(0xffffffffu, l0, 1);
    l0 += __shfl_xor_sync(0xffffffffu, l0, 2);
    l1 += __shfl_xor_sync(0xffffffffu, l1, 1);
    l1 += __shfl_xor_sync(0xffffffffu, l1, 2);

    float* pd = part + (size_t)(z * 16 + bh) * N_ * DH_;
#pragma unroll
    for (int nt = 0; nt < 8; nt++) {
        int col = nt * 8 + (lane & 3) * 2;
        *(float2*)&pd[(size_t)qrow * DH_ + col]       = make_float2(o[nt * 4 + 0], o[nt * 4 + 1]);
        *(float2*)&pd[(size_t)(qrow + 8) * DH_ + col] = make_float2(o[nt * 4 + 2], o[nt * 4 + 3]);
    }
    if ((lane & 3) == 0) {
        lsum[(z * 16 + bh) * N_ + qrow]     = l0;
        lsum[(z * 16 + bh) * N_ + qrow + 8] = l1;
    }
}

// =================================================================
// Combine kv-split partials -> aohi/aolo (batch 0 uses z=0,1 only)
// =================================================================
__global__ __launch_bounds__(128) void attn_reduce(
    const float* __restrict__ part, const float* __restrict__ lsum,
    bf* __restrict__ aoh, bf* __restrict__ aol)
{
    int row = blockIdx.x * 128 + threadIdx.x;
    int bh = row >> 10, qi = row & 1023;
    int b = bh >> 3, h = bh & 7;
    const int zmax = (b == 0) ? 2 : KVSPLIT;

    float l = 0.f;
    for (int z = 0; z < zmax; z++) l += lsum[(z * 16 + bh) * N_ + qi];
    float inv = 1.0f / l;

    size_t dbase = (size_t)(b * N_ + qi) * QD_ + h * DH_;
#pragma unroll
    for (int d4 = 0; d4 < 16; d4++) {
        float4 acc = make_float4(0.f, 0.f, 0.f, 0.f);
        for (int z = 0; z < zmax; z++) {
            const float4 p4 = ((const float4*)(part +
                ((size_t)(z * 16 + bh) * N_ + qi) * DH_))[d4];
            acc.x += p4.x; acc.y += p4.y; acc.z += p4.z; acc.w += p4.w;
        }
        bf2 h0, l0, h1, l1;
        split2(acc.x * inv, acc.y * inv, h0, l0);
        split2(acc.z * inv, acc.w * inv, h1, l1);
        *(bf2*)&aoh[dbase + d4 * 4]     = h0;
        *(bf2*)&aol[dbase + d4 * 4]     = l0;
        *(bf2*)&aoh[dbase + d4 * 4 + 2] = h1;
        *(bf2*)&aol[dbase + d4 * 4 + 2] = l1;
    }
}

// =================================================================
extern "C" void kernel_launch(void* const* d_in, const int* in_sizes, int n_in,
                              void* d_out, int out_size)
{
    const float* x    = (const float*)d_in[0];
    const float* mask = (const float*)d_in[1];
    const float* Wq   = (const float*)d_in[2];
    const float* Wk   = (const float*)d_in[3];
    const float* Wv   = (const float*)d_in[4];
    const float* Wo   = (const float*)d_in[5];
    const float* bo   = (const float*)d_in[6];

    float *m, *cnt, *sc, *sh, *prt, *lsm, *pad;
    bf *xhi, *xlo, *whi, *wlo, *qhi, *qlo, *khi, *klo, *vhi, *vlo, *aohi, *aolo;
    cudaGetSymbolAddress((void**)&m,    g_m);
    cudaGetSymbolAddress((void**)&cnt,  g_cnt);
    cudaGetSymbolAddress((void**)&sc,   g_scale);
    cudaGetSymbolAddress((void**)&sh,   g_shift);
    cudaGetSymbolAddress((void**)&prt,  g_part);
    cudaGetSymbolAddress((void**)&lsm,  g_lsum);
    cudaGetSymbolAddress((void**)&pad,  g_padain);
    cudaGetSymbolAddress((void**)&xhi,  g_xhi);
    cudaGetSymbolAddress((void**)&xlo,  g_xlo);
    cudaGetSymbolAddress((void**)&whi,  g_whi);
    cudaGetSymbolAddress((void**)&wlo,  g_wlo);
    cudaGetSymbolAddress((void**)&qhi,  g_qhi);
    cudaGetSymbolAddress((void**)&qlo,  g_qlo);
    cudaGetSymbolAddress((void**)&khi,  g_khi);
    cudaGetSymbolAddress((void**)&klo,  g_klo);
    cudaGetSymbolAddress((void**)&vhi,  g_vhi);
    cudaGetSymbolAddress((void**)&vlo,  g_vlo);
    cudaGetSymbolAddress((void**)&aohi, g_aohi);
    cudaGetSymbolAddress((void**)&aolo, g_aolo);

    cudaFuncSetAttribute(gemm_mma<0>, cudaFuncAttributeMaxDynamicSharedMemorySize, GEMM_SMEM);
    cudaFuncSetAttribute(gemm_mma<1>, cudaFuncAttributeMaxDynamicSharedMemorySize, GEMM_SMEM);
    cudaFuncSetAttribute(attn_mma, cudaFuncAttributeMaxDynamicSharedMemorySize, ATTN_SMEM);

    const int M = B_ * N_;        // 2048
    const int WS = QD_ * QD_;     // 262144

    // fused conversions + mask (block 2048 handles the mask)
    cvt_all<<<2049, 256>>>((const float4*)x,
                           (const float4*)Wq, (const float4*)Wk,
                           (const float4*)Wv, (const float4*)Wo,
                           (bf2*)xhi, (bf2*)xlo, (bf2*)whi, (bf2*)wlo,
                           mask, m, cnt);

    // fused QKV projection (N = 1536), 128x64 tiles, BK=64
    gemm_mma<0><<<dim3(24, 16), 256, GEMM_SMEM>>>(
        xhi, xlo, whi, wlo, nullptr, nullptr,
        qhi, qlo, khi, klo, vhi, vlo, M, QD_);

    adain_partial<<<256, 256>>>(khi, klo, vhi, vlo, m, pad);
    adain_final<<<8, 128>>>(pad, cnt, sc, sh);
    adain_apply2<<<2048, 256>>>(khi, klo, vhi, vlo, m, sc, sh);

    attn_mma<<<dim3(8, 16, KVSPLIT), 256, ATTN_SMEM>>>(qhi, khi, vhi, vlo, m, prt, lsm);
    attn_reduce<<<128, 128>>>(prt, lsm, aohi, aolo);

    gemm_mma<1><<<dim3(8, 16), 256, GEMM_SMEM>>>(
        aohi, aolo, whi + 3 * WS, wlo + 3 * WS, bo, (float*)d_out,
        nullptr, nullptr, nullptr, nullptr, nullptr, nullptr, M, QD_);
}

// round 14
// speedup vs baseline: 1.0853x; 1.0303x over previous
#include <cuda_runtime.h>
#include <cuda_bf16.h>
#include <math.h>
#include <stdint.h>

// Problem constants
#define B_    2
#define N_    1024
#define QD_   512
#define H_    8
#define DH_   64
#define SCALE_ 0.125f   // DH^-0.5
#define KVSPLIT 4

// ---------------- PTX helpers ----------------
__device__ __forceinline__ uint32_t smem_u32(const void* p) {
    uint32_t a;
    asm("{ .reg .u64 t; cvta.to.shared.u64 t, %1; cvt.u32.u64 %0, t; }" : "=r"(a) : "l"(p));
    return a;
}
__device__ __forceinline__ void cp16(uint32_t dst, const void* src) {
    asm volatile("cp.async.cg.shared.global [%0], [%1], 16;" :: "r"(dst), "l"(src) : "memory");
}
#define CP_COMMIT asm volatile("cp.async.commit_group;" ::: "memory")
#define CP_WAIT1  asm volatile("cp.async.wait_group 1;" ::: "memory")
#define CP_WAIT0  asm volatile("cp.async.wait_group 0;" ::: "memory")

__device__ __forceinline__ void ldsm4(uint32_t* r, uint32_t a) {
    asm volatile("ldmatrix.sync.aligned.m8n8.x4.shared.b16 {%0,%1,%2,%3}, [%4];"
                 : "=r"(r[0]), "=r"(r[1]), "=r"(r[2]), "=r"(r[3]) : "r"(a));
}
__device__ __forceinline__ void ldsm4t(uint32_t* r, uint32_t a) {
    asm volatile("ldmatrix.sync.aligned.m8n8.x4.trans.shared.b16 {%0,%1,%2,%3}, [%4];"
                 : "=r"(r[0]), "=r"(r[1]), "=r"(r[2]), "=r"(r[3]) : "r"(a));
}
__device__ __forceinline__ void mma16816(float* c, const uint32_t* a, uint32_t b0, uint32_t b1) {
    asm volatile(
        "mma.sync.aligned.m16n8k16.row.col.f32.bf16.bf16.f32 "
        "{%0,%1,%2,%3}, {%4,%5,%6,%7}, {%8,%9}, {%0,%1,%2,%3};"
        : "+f"(c[0]), "+f"(c[1]), "+f"(c[2]), "+f"(c[3])
        : "r"(a[0]), "r"(a[1]), "r"(a[2]), "r"(a[3]), "r"(b0), "r"(b1));
}
__device__ __forceinline__ uint32_t pkbf(float lo, float hi) {
    uint32_t r;
    asm("cvt.rn.satfinite.bf16x2.f32 %0, %1, %2;" : "=r"(r) : "f"(hi), "f"(lo));
    return r;
}
__device__ __forceinline__ float lo16f(uint32_t u) { return __uint_as_float(u << 16); }
__device__ __forceinline__ float hi16f(uint32_t u) { return __uint_as_float(u & 0xffff0000u); }

typedef __nv_bfloat16 bf;
typedef __nv_bfloat162 bf2;

// ---------------- scratch ----------------
__device__ float g_m [N_];
__device__ float g_cnt[1];
__device__ float g_scale[2*QD_];
__device__ float g_shift[2*QD_];
__device__ float g_padain[2*QD_*32*4];    // [tensor][ch][rowgrp(32)][4]
__device__ bf g_xhi[B_*N_*QD_], g_xlo[B_*N_*QD_];
__device__ bf g_whi[4][QD_*QD_], g_wlo[4][QD_*QD_];
__device__ bf g_qhi[B_*N_*QD_], g_qlo[B_*N_*QD_];
__device__ bf g_khi[B_*N_*QD_], g_klo[B_*N_*QD_];
__device__ bf g_vhi[B_*N_*QD_], g_vlo[B_*N_*QD_];
__device__ bf g_aohi[B_*N_*QD_], g_aolo[B_*N_*QD_];
__device__ float g_part[KVSPLIT*16*N_*DH_];
__device__ float g_lsum[KVSPLIT*16*N_];

// =================================================================
// fp32 -> bf16 hi/lo split helpers
// =================================================================
__device__ __forceinline__ void split2(float a, float b, bf2& h2, bf2& l2) {
    bf h0 = __float2bfloat16(a), h1 = __float2bfloat16(b);
    h2.x = h0; h2.y = h1;
    l2.x = __float2bfloat16(a - __bfloat162float(h0));
    l2.y = __float2bfloat16(b - __bfloat162float(h1));
}

// Fused conversion + mask kernel:
// blocks [0, 2048): x (262144 f4) then W0..W3 (4 x 65536 f4)
// block 2048: mask resize (64x64 -> 32x32 nearest) + count
__global__ __launch_bounds__(256) void cvt_all(
    const float4* __restrict__ x,
    const float4* __restrict__ w0, const float4* __restrict__ w1,
    const float4* __restrict__ w2, const float4* __restrict__ w3,
    bf2* __restrict__ xhi, bf2* __restrict__ xlo,
    bf2* __restrict__ whi, bf2* __restrict__ wlo,
    const float* __restrict__ mask, float* __restrict__ m, float* __restrict__ cnt)
{
    if (blockIdx.x == 2048) {
        int t = threadIdx.x;
        float s = 0.f;
#pragma unroll
        for (int j = 0; j < 4; j++) {
            int i = t * 4 + j;
            int r = i >> 5, c = i & 31;
            float mv = mask[(r * 2) * 64 + c * 2];
            m[i] = mv;
            s += mv;
        }
        __shared__ float red[256];
        red[t] = s;
        __syncthreads();
        for (int st = 128; st > 0; st >>= 1) {
            if (t < st) red[t] += red[t + st];
            __syncthreads();
        }
        if (t == 0) cnt[0] = red[0];
        return;
    }

    int i = blockIdx.x * 256 + threadIdx.x;      // [0, 524288)
    const float4* src;
    bf2 *hi, *lo;
    size_t o;
    if (i < 262144) {
        src = x + i; hi = xhi; lo = xlo; o = (size_t)i * 2;
    } else {
        int j = i - 262144;
        int t = j >> 16, jj = j & 65535;
        src = ((t == 0) ? w0 : (t == 1) ? w1 : (t == 2) ? w2 : w3) + jj;
        hi = whi; lo = wlo; o = (size_t)j * 2;
    }
    float4 v = *src;
    bf2 h0, l0, h1, l1;
    split2(v.x, v.y, h0, l0);
    split2(v.z, v.w, h1, l1);
    hi[o] = h0; hi[o+1] = h1;
    lo[o] = l0; lo[o+1] = l1;
}

// =================================================================
// mma.sync GEMM, tile 128x64, BK=64, 2-stage cp.async, split-bf16.
// MODE 0: fused QKV -> bf16 hi/lo; MODE 1: fp32 + bias.
// =================================================================
#define S_AH(s) ((s)*55296 + 0)
#define S_AL(s) ((s)*55296 + 18432)
#define S_BH(s) ((s)*55296 + 36864)
#define S_BL(s) ((s)*55296 + 46080)
#define GEMM_SMEM 110592

template<int MODE>
__global__ __launch_bounds__(256, 2) void gemm_mma(
    const bf* __restrict__ Ahi, const bf* __restrict__ Alo,
    const bf* __restrict__ Bhi, const bf* __restrict__ Blo,
    const float* __restrict__ bias, float* __restrict__ Cf,
    bf* __restrict__ O0h, bf* __restrict__ O0l,
    bf* __restrict__ O1h, bf* __restrict__ O1l,
    bf* __restrict__ O2h, bf* __restrict__ O2l,
    int M, int K)
{
    extern __shared__ __align__(16) char sg[];
    const uint32_t sb = smem_u32(sg);
    const int tid = threadIdx.x;
    const int warp = tid >> 5, lane = tid & 31;
    const int wm = warp & 3, wn = warp >> 2;
    const int bm = blockIdx.y * 128, bn = blockIdx.x * 64;
    const int grp = lane >> 3, lr = lane & 7;

    auto load_stage = [&](int s, int k0) {
#pragma unroll
        for (int i = 0; i < 4; i++) {           // A hi
            int c = tid + i * 256;
            int r = c >> 3, col = c & 7;
            cp16(sb + S_AH(s) + r * 144 + col * 16,
                 Ahi + (size_t)(bm + r) * K + k0 + col * 8);
        }
#pragma unroll
        for (int i = 0; i < 4; i++) {           // A lo
            int c = tid + i * 256;
            int r = c >> 3, col = c & 7;
            cp16(sb + S_AL(s) + r * 144 + col * 16,
                 Alo + (size_t)(bm + r) * K + k0 + col * 8);
        }
#pragma unroll
        for (int i = 0; i < 2; i++) {           // B hi
            int c = tid + i * 256;
            int r = c >> 3, col = c & 7;
            cp16(sb + S_BH(s) + r * 144 + col * 16,
                 Bhi + (size_t)(bn + r) * K + k0 + col * 8);
        }
#pragma unroll
        for (int i = 0; i < 2; i++) {           // B lo
            int c = tid + i * 256;
            int r = c >> 3, col = c & 7;
            cp16(sb + S_BL(s) + r * 144 + col * 16,
                 Blo + (size_t)(bn + r) * K + k0 + col * 8);
        }
    };

    float acc[32];
#pragma unroll
    for (int i = 0; i < 32; i++) acc[i] = 0.f;

    const int ksteps = K >> 6;    // 8 for K=512
    load_stage(0, 0);  CP_COMMIT;
    load_stage(1, 64); CP_COMMIT;

    const uint32_t aaddr = (wm * 32 + (lane & 15)) * 144 + (lane >> 4) * 16;
    const int rowB = wn * 32 + ((grp >> 1) << 3) + lr;
    const int colB = (grp & 1) * 16;

    for (int kt = 0; kt < ksteps; kt++) {
        if (kt == ksteps - 1) { CP_WAIT0; } else { CP_WAIT1; }
        __syncthreads();
        const int s = kt & 1;
        const uint32_t ahb = sb + S_AH(s), alb = sb + S_AL(s);
        const uint32_t bhb = sb + S_BH(s), blb = sb + S_BL(s);

#pragma unroll
        for (int kb = 0; kb < 4; kb++) {
            uint32_t ah[2][4], al[2][4];
#pragma unroll
            for (int mt = 0; mt < 2; mt++) {
                ldsm4(ah[mt], ahb + aaddr + mt * 16 * 144 + kb * 32);
                ldsm4(al[mt], alb + aaddr + mt * 16 * 144 + kb * 32);
            }
#pragma unroll
            for (int p = 0; p < 2; p++) {
                uint32_t bhf[4], blf[4];
                ldsm4(bhf, bhb + (rowB + p * 16) * 144 + kb * 32 + colB);
                ldsm4(blf, blb + (rowB + p * 16) * 144 + kb * 32 + colB);
#pragma unroll
                for (int mt = 0; mt < 2; mt++) {
#pragma unroll
                    for (int sub = 0; sub < 2; sub++) {
                        float* c = &acc[(mt * 4 + p * 2 + sub) * 4];
                        mma16816(c, ah[mt], bhf[sub * 2], bhf[sub * 2 + 1]);
                        mma16816(c, al[mt], bhf[sub * 2], bhf[sub * 2 + 1]);
                        mma16816(c, ah[mt], blf[sub * 2], blf[sub * 2 + 1]);
                    }
                }
            }
        }
        __syncthreads();
        if (kt + 2 < ksteps) { load_stage(s, (kt + 2) * 64); CP_COMMIT; }
    }

    if (MODE == 0) {
        const int which = bn >> 9;
        bf* OH = (which == 0) ? O0h : (which == 1) ? O1h : O2h;
        bf* OL = (which == 0) ? O0l : (which == 1) ? O1l : O2l;
        const int cbase = (bn & 511) + wn * 32;
#pragma unroll
        for (int mt = 0; mt < 2; mt++) {
#pragma unroll
            for (int nt = 0; nt < 4; nt++) {
                const float* c = &acc[(mt * 4 + nt) * 4];
                int row = bm + wm * 32 + mt * 16 + (lane >> 2);
                int col = cbase + nt * 8 + (lane & 3) * 2;
                bf2 h0, l0, h1, l1;
                split2(c[0], c[1], h0, l0);
                split2(c[2], c[3], h1, l1);
                *(bf2*)&OH[(size_t)row * QD_ + col] = h0;
                *(bf2*)&OL[(size_t)row * QD_ + col] = l0;
                *(bf2*)&OH[(size_t)(row + 8) * QD_ + col] = h1;
                *(bf2*)&OL[(size_t)(row + 8) * QD_ + col] = l1;
            }
        }
    } else {
        const int cbase = bn + wn * 32;
#pragma unroll
        for (int mt = 0; mt < 2; mt++) {
#pragma unroll
            for (int nt = 0; nt < 4; nt++) {
                const float* c = &acc[(mt * 4 + nt) * 4];
                int row = bm + wm * 32 + mt * 16 + (lane >> 2);
                int col = cbase + nt * 8 + (lane & 3) * 2;
                float b0 = bias[col], b1 = bias[col + 1];
                *(float2*)&Cf[(size_t)row * QD_ + col]       = make_float2(c[0] + b0, c[1] + b1);
                *(float2*)&Cf[(size_t)(row + 8) * QD_ + col] = make_float2(c[2] + b0, c[3] + b1);
            }
        }
    }
}

// =================================================================
// AdaIN stats phase 1: partial sums (256 blocks, bf2 channel pairs)
// =================================================================
__global__ __launch_bounds__(256) void adain_partial(
    const bf* __restrict__ khi, const bf* __restrict__ klo,
    const bf* __restrict__ vhi, const bf* __restrict__ vlo,
    const float* __restrict__ m, float* __restrict__ padain)
{
    const int tensor = blockIdx.x >> 7;
    const int cg = (blockIdx.x >> 5) & 3;
    const int rg = blockIdx.x & 31;
    const bf* Th = tensor ? vhi : khi;
    const bf* Tl = tensor ? vlo : klo;
    const int tch = threadIdx.x & 63;
    const int ch = cg * 128 + tch * 2;
    const int rp = threadIdx.x >> 6;
    const int row0 = rg * 32;

    float rs0 = 0.f, rss0 = 0.f, fs0 = 0.f, fss0 = 0.f;
    float rs1 = 0.f, rss1 = 0.f, fs1 = 0.f, fss1 = 0.f;
#pragma unroll
    for (int r = rp; r < 32; r += 4) {
        int row = row0 + r;
        bf2 rh = *(const bf2*)&Th[(size_t)row * QD_ + ch];
        bf2 rl = *(const bf2*)&Tl[(size_t)row * QD_ + ch];
        bf2 fh = *(const bf2*)&Th[(size_t)(N_ + row) * QD_ + ch];
        bf2 fl = *(const bf2*)&Tl[(size_t)(N_ + row) * QD_ + ch];
        float mv = m[row];
        float rv0 = __bfloat162float(rh.x) + __bfloat162float(rl.x);
        float rv1 = __bfloat162float(rh.y) + __bfloat162float(rl.y);
        float fv0 = __bfloat162float(fh.x) + __bfloat162float(fl.x);
        float fv1 = __bfloat162float(fh.y) + __bfloat162float(fl.y);
        rs0 += rv0; rss0 += rv0 * rv0;
        rs1 += rv1; rss1 += rv1 * rv1;
        fs0 += mv * fv0; fss0 += mv * fv0 * fv0;
        fs1 += mv * fv1; fss1 += mv * fv1 * fv1;
    }
    __shared__ float4 redA[256], redB[256];
    redA[threadIdx.x] = make_float4(rs0, rss0, fs0, fss0);
    redB[threadIdx.x] = make_float4(rs1, rss1, fs1, fss1);
    __syncthreads();
    if (rp == 0) {
        float4 a0 = redA[tch], a1 = redA[tch + 64], a2 = redA[tch + 128], a3 = redA[tch + 192];
        float4 b0 = redB[tch], b1 = redB[tch + 64], b2 = redB[tch + 128], b3 = redB[tch + 192];
        float4 oA = make_float4(a0.x + a1.x + a2.x + a3.x, a0.y + a1.y + a2.y + a3.y,
                                a0.z + a1.z + a2.z + a3.z, a0.w + a1.w + a2.w + a3.w);
        float4 oB = make_float4(b0.x + b1.x + b2.x + b3.x, b0.y + b1.y + b2.y + b3.y,
                                b0.z + b1.z + b2.z + b3.z, b0.w + b1.w + b2.w + b3.w);
        *(float4*)&padain[(((size_t)tensor * QD_ + ch)     * 32 + rg) * 4] = oA;
        *(float4*)&padain[(((size_t)tensor * QD_ + ch + 1) * 32 + rg) * 4] = oB;
    }
}

// =================================================================
// AdaIN stats phase 2: finalize scale/shift.
// One warp per channel: grid 128 x 256 thr (8 warps/block, 1024 warps).
// Lane i loads rowgroup-i partial; 5-level butterfly reduce.
// =================================================================
__global__ __launch_bounds__(256) void adain_final(
    const float* __restrict__ padain, const float* __restrict__ cntp,
    float* __restrict__ scaleArr, float* __restrict__ shiftArr)
{
    const int warp = (blockIdx.x * 256 + threadIdx.x) >> 5;   // channel [0, 1024)
    const int lane = threadIdx.x & 31;

    float4 p = *(const float4*)&padain[((size_t)warp * 32 + lane) * 4];
    float R = p.x, RS = p.y, F = p.z, FS = p.w;
#pragma unroll
    for (int st = 16; st > 0; st >>= 1) {
        R  += __shfl_xor_sync(0xffffffffu, R,  st);
        RS += __shfl_xor_sync(0xffffffffu, RS, st);
        F  += __shfl_xor_sync(0xffffffffu, F,  st);
        FS += __shfl_xor_sync(0xffffffffu, FS, st);
    }
    if (lane == 0) {
        float cnt = cntp[0];
        float ref_mean = R * (1.0f / N_);
        float ref_var  = (RS - (float)N_ * ref_mean * ref_mean) * (1.0f / (N_ - 1));
        float ref_std  = sqrtf(fmaxf(ref_var, 0.f));
        float f_mean   = F / cnt;
        float f_var    = (FS - cnt * f_mean * f_mean) / (cnt - 1.0f);
        float f_std    = sqrtf(fmaxf(f_var, 0.f));
        float sc = ref_std / f_std;
        scaleArr[warp] = sc;
        shiftArr[warp] = ref_mean - f_mean * sc;
    }
}

// =================================================================
// AdaIN apply in-place on bf16 hi/lo (masked batch-1 rows)
// =================================================================
__global__ __launch_bounds__(256) void adain_apply2(
    bf* __restrict__ khi, bf* __restrict__ klo,
    bf* __restrict__ vhi, bf* __restrict__ vlo,
    const float* __restrict__ m,
    const float* __restrict__ scaleArr, const float* __restrict__ shiftArr)
{
    const int row = blockIdx.x & 1023;
    const int tensor = blockIdx.x >> 10;
    if (m[row] < 0.5f) return;
    bf* Th = tensor ? vhi : khi;
    bf* Tl = tensor ? vlo : klo;
    const int ch = threadIdx.x * 2;
    const size_t off = (size_t)(N_ + row) * QD_ + ch;
    bf2 h = *(bf2*)&Th[off];
    bf2 l = *(bf2*)&Tl[off];
    float v0 = __bfloat162float(h.x) + __bfloat162float(l.x);
    float v1 = __bfloat162float(h.y) + __bfloat162float(l.y);
    const float2 sc = *(const float2*)&scaleArr[tensor * QD_ + ch];
    const float2 sh = *(const float2*)&shiftArr[tensor * QD_ + ch];
    v0 = fmaf(v0, sc.x, sh.x);
    v1 = fmaf(v1, sc.y, sh.y);
    bf2 nh, nl;
    split2(v0, v1, nh, nl);
    *(bf2*)&Th[off] = nh;
    *(bf2*)&Tl[off] = nl;
}

// =================================================================
// Flash attention via mma.sync, no-max softmax.
// QK 1-term: s = qh·kh.  PV 3-term (vlo kept).
// grid (8 qtiles, 16 bh, 4 kvsplit of 8 tiles); b==0 z>=2 exact skip.
// smem 73728 -> 3 CTAs/SM.
// =================================================================
#define AQH 0
#define ATS(s) (18432 + (s) * 27648)
#define ATTN_SMEM 73728

__global__ __launch_bounds__(256, 3) void attn_mma(
    const bf* __restrict__ qhi,
    const bf* __restrict__ khi,
    const bf* __restrict__ vhi, const bf* __restrict__ vlo,
    const float* __restrict__ m,
    float* __restrict__ part, float* __restrict__ lsum)
{
    extern __shared__ __align__(16) char sma[];
    const uint32_t sb = smem_u32(sma);
    const int tid = threadIdx.x, wid = tid >> 5, lane = tid & 31;
    const int bh = blockIdx.y, b = bh >> 3, h = bh & 7;
    const int z = blockIdx.z;
    if (b == 0 && z >= 2) return;   // duplicate-key half: exact skip
    const int q0 = blockIdx.x * 128;
    const int grp = lane >> 3, lr = lane & 7;

    // ---- Q tile (hi only, 128 rows) ----
#pragma unroll
    for (int i = 0; i < 4; i++) {
        int c = tid + i * 256;
        int r = c >> 3, col = c & 7;
        const bf* src = qhi + (size_t)(b * N_ + q0 + r) * QD_ + h * DH_ + col * 8;
        cp16(sb + AQH + r * 144 + col * 16, src);
    }

    auto load_tile = [&](int s, int tileIdx) {
        int j0 = tileIdx * 64;
        int grow = (j0 < N_) ? (b * N_ + j0) : (j0 - N_);
        uint32_t tb = sb + ATS(s);
#pragma unroll
        for (int i = 0; i < 6; i++) {
            int c = tid + i * 256;
            int mt = c >> 9, r = (c >> 3) & 63, col = c & 7;
            const bf* srcb = (mt == 0) ? khi : (mt == 1) ? vhi : vlo;
            cp16(tb + mt * 9216 + r * 144 + col * 16,
                 srcb + (size_t)(grow + r) * QD_ + h * DH_ + col * 8);
        }
    };

    load_tile(0, z * 8);     CP_COMMIT;
    load_tile(1, z * 8 + 1); CP_COMMIT;
    CP_WAIT1;
    __syncthreads();

    // ---- Q fragments ----
    uint32_t qh[16];
    {
        uint32_t base = sb + AQH + (wid * 16 + (lane & 15)) * 144 + (lane >> 4) * 16;
#pragma unroll
        for (int k16 = 0; k16 < 4; k16++) ldsm4(&qh[k16 * 4], base + k16 * 32);
    }

    const int r4 = lane >> 2;
    const int qrow = q0 + wid * 16 + r4;
    float flag0 = 1.f, flag1 = 1.f;
    if (b == 1 && z >= 2) {
        flag0 = (m[qrow]     < 0.5f) ? 0.f : 1.f;
        flag1 = (m[qrow + 8] < 0.5f) ? 0.f : 1.f;
    }

    float o[32];
#pragma unroll
    for (int i = 0; i < 32; i++) o[i] = 0.f;
    float l0 = 0.f, l1 = 0.f;

    const int rowKb = ((grp >> 1) << 3) + lr;
    const int colK  = (grp & 1) * 16;
    const int rowVb = ((grp & 1) << 3) + lr;
    const int colV  = (grp >> 1) * 16;

    for (int kt = 0; kt < 8; kt++) {
        const int s = kt & 1;
        if (kt > 0) {
            if (kt == 7) { CP_WAIT0; } else { CP_WAIT1; }
            __syncthreads();
        }
        const uint32_t khb = sb + ATS(s);
        const uint32_t vhb = khb + 9216;
        const uint32_t vlb = khb + 18432;

#pragma unroll
        for (int kk = 0; kk < 4; kk++) {
            float s0[4] = {0.f, 0.f, 0.f, 0.f};
            float s1[4] = {0.f, 0.f, 0.f, 0.f};
            const uint32_t kro = (kk * 16 + rowKb) * 144 + colK;
#pragma unroll
            for (int k16 = 0; k16 < 4; k16++) {
                uint32_t bhf[4];
                ldsm4(bhf, khb + kro + k16 * 32);
                mma16816(s0, &qh[k16 * 4], bhf[0], bhf[1]);
                mma16816(s1, &qh[k16 * 4], bhf[2], bhf[3]);
            }
            s0[0] = __expf(s0[0] * SCALE_) * flag0;
            s0[1] = __expf(s0[1] * SCALE_) * flag0;
            s0[2] = __expf(s0[2] * SCALE_) * flag1;
            s0[3] = __expf(s0[3] * SCALE_) * flag1;
            s1[0] = __expf(s1[0] * SCALE_) * flag0;
            s1[1] = __expf(s1[1] * SCALE_) * flag0;
            s1[2] = __expf(s1[2] * SCALE_) * flag1;
            s1[3] = __expf(s1[3] * SCALE_) * flag1;
            l0 += s0[0] + s0[1] + s1[0] + s1[1];
            l1 += s0[2] + s0[3] + s1[2] + s1[3];

            uint32_t ph[4], pl[4];
            ph[0] = pkbf(s0[0], s0[1]);
            pl[0] = pkbf(s0[0] - lo16f(ph[0]), s0[1] - hi16f(ph[0]));
            ph[1] = pkbf(s0[2], s0[3]);
            pl[1] = pkbf(s0[2] - lo16f(ph[1]), s0[3] - hi16f(ph[1]));
            ph[2] = pkbf(s1[0], s1[1]);
            pl[2] = pkbf(s1[0] - lo16f(ph[2]), s1[1] - hi16f(ph[2]));
            ph[3] = pkbf(s1[2], s1[3]);
            pl[3] = pkbf(s1[2] - lo16f(ph[3]), s1[3] - hi16f(ph[3]));

            const uint32_t vro = (kk * 16 + rowVb) * 144 + colV;
#pragma unroll
            for (int dp = 0; dp < 4; dp++) {
                uint32_t vhf[4], vlf[4];
                ldsm4t(vhf, vhb + vro + dp * 32);
                ldsm4t(vlf, vlb + vro + dp * 32);
                mma16816(&o[dp * 8],     ph, vhf[0], vhf[1]);
                mma16816(&o[dp * 8 + 4], ph, vhf[2], vhf[3]);
                mma16816(&o[dp * 8],     pl, vhf[0], vhf[1]);
                mma16816(&o[dp * 8 + 4], pl, vhf[2], vhf[3]);
                mma16816(&o[dp * 8],     ph, vlf[0], vlf[1]);
                mma16816(&o[dp * 8 + 4], ph, vlf[2], vlf[3]);
            }
        }
        __syncthreads();
        if (kt + 2 < 8) { load_tile(s, z * 8 + kt + 2); CP_COMMIT; }
    }

    // ---- epilogue ----
    l0 += __shfl_xor_sync(0xffffffffu, l0, 1);
    l0 += __shfl_xor_sync(0xffffffffu, l0, 2);
    l1 += __shfl_xor_sync(0xffffffffu, l1, 1);
    l1 += __shfl_xor_sync(0xffffffffu, l1, 2);

    float* pd = part + (size_t)(z * 16 + bh) * N_ * DH_;
#pragma unroll
    for (int nt = 0; nt < 8; nt++) {
        int col = nt * 8 + (lane & 3) * 2;
        *(float2*)&pd[(size_t)qrow * DH_ + col]       = make_float2(o[nt * 4 + 0], o[nt * 4 + 1]);
        *(float2*)&pd[(size_t)(qrow + 8) * DH_ + col] = make_float2(o[nt * 4 + 2], o[nt * 4 + 3]);
    }
    if ((lane & 3) == 0) {
        lsum[(z * 16 + bh) * N_ + qrow]     = l0;
        lsum[(z * 16 + bh) * N_ + qrow + 8] = l1;
    }
}

// =================================================================
// Combine kv-split partials -> aohi/aolo (batch 0 uses z=0,1 only)
// grid 256 x 64 thr
// =================================================================
__global__ __launch_bounds__(64) void attn_reduce(
    const float* __restrict__ part, const float* __restrict__ lsum,
    bf* __restrict__ aoh, bf* __restrict__ aol)
{
    int row = blockIdx.x * 64 + threadIdx.x;
    int bh = row >> 10, qi = row & 1023;
    int b = bh >> 3, h = bh & 7;
    const int zmax = (b == 0) ? 2 : KVSPLIT;

    float l = 0.f;
    for (int z = 0; z < zmax; z++) l += lsum[(z * 16 + bh) * N_ + qi];
    float inv = 1.0f / l;

    size_t dbase = (size_t)(b * N_ + qi) * QD_ + h * DH_;
#pragma unroll
    for (int d4 = 0; d4 < 16; d4++) {
        float4 acc = make_float4(0.f, 0.f, 0.f, 0.f);
        for (int z = 0; z < zmax; z++) {
            const float4 p4 = ((const float4*)(part +
                ((size_t)(z * 16 + bh) * N_ + qi) * DH_))[d4];
            acc.x += p4.x; acc.y += p4.y; acc.z += p4.z; acc.w += p4.w;
        }
        bf2 h0, l0, h1, l1;
        split2(acc.x * inv, acc.y * inv, h0, l0);
        split2(acc.z * inv, acc.w * inv, h1, l1);
        *(bf2*)&aoh[dbase + d4 * 4]     = h0;
        *(bf2*)&aol[dbase + d4 * 4]     = l0;
        *(bf2*)&aoh[dbase + d4 * 4 + 2] = h1;
        *(bf2*)&aol[dbase + d4 * 4 + 2] = l1;
    }
}

// =================================================================
extern "C" void kernel_launch(void* const* d_in, const int* in_sizes, int n_in,
                              void* d_out, int out_size)
{
    const float* x    = (const float*)d_in[0];
    const float* mask = (const float*)d_in[1];
    const float* Wq   = (const float*)d_in[2];
    const float* Wk   = (const float*)d_in[3];
    const float* Wv   = (const float*)d_in[4];
    const float* Wo   = (const float*)d_in[5];
    const float* bo   = (const float*)d_in[6];

    float *m, *cnt, *sc, *sh, *prt, *lsm, *pad;
    bf *xhi, *xlo, *whi, *wlo, *qhi, *qlo, *khi, *klo, *vhi, *vlo, *aohi, *aolo;
    cudaGetSymbolAddress((void**)&m,    g_m);
    cudaGetSymbolAddress((void**)&cnt,  g_cnt);
    cudaGetSymbolAddress((void**)&sc,   g_scale);
    cudaGetSymbolAddress((void**)&sh,   g_shift);
    cudaGetSymbolAddress((void**)&prt,  g_part);
    cudaGetSymbolAddress((void**)&lsm,  g_lsum);
    cudaGetSymbolAddress((void**)&pad,  g_padain);
    cudaGetSymbolAddress((void**)&xhi,  g_xhi);
    cudaGetSymbolAddress((void**)&xlo,  g_xlo);
    cudaGetSymbolAddress((void**)&whi,  g_whi);
    cudaGetSymbolAddress((void**)&wlo,  g_wlo);
    cudaGetSymbolAddress((void**)&qhi,  g_qhi);
    cudaGetSymbolAddress((void**)&qlo,  g_qlo);
    cudaGetSymbolAddress((void**)&khi,  g_khi);
    cudaGetSymbolAddress((void**)&klo,  g_klo);
    cudaGetSymbolAddress((void**)&vhi,  g_vhi);
    cudaGetSymbolAddress((void**)&vlo,  g_vlo);
    cudaGetSymbolAddress((void**)&aohi, g_aohi);
    cudaGetSymbolAddress((void**)&aolo, g_aolo);

    cudaFuncSetAttribute(gemm_mma<0>, cudaFuncAttributeMaxDynamicSharedMemorySize, GEMM_SMEM);
    cudaFuncSetAttribute(gemm_mma<1>, cudaFuncAttributeMaxDynamicSharedMemorySize, GEMM_SMEM);
    cudaFuncSetAttribute(attn_mma, cudaFuncAttributeMaxDynamicSharedMemorySize, ATTN_SMEM);

    const int M = B_ * N_;        // 2048
    const int WS = QD_ * QD_;     // 262144

    // fused conversions + mask (block 2048 handles the mask)
    cvt_all<<<2049, 256>>>((const float4*)x,
                           (const float4*)Wq, (const float4*)Wk,
                           (const float4*)Wv, (const float4*)Wo,
                           (bf2*)xhi, (bf2*)xlo, (bf2*)whi, (bf2*)wlo,
                           mask, m, cnt);

    // fused QKV projection (N = 1536), 128x64 tiles, BK=64
    gemm_mma<0><<<dim3(24, 16), 256, GEMM_SMEM>>>(
        xhi, xlo, whi, wlo, nullptr, nullptr,
        qhi, qlo, khi, klo, vhi, vlo, M, QD_);

    adain_partial<<<256, 256>>>(khi, klo, vhi, vlo, m, pad);
    adain_final<<<128, 256>>>(pad, cnt, sc, sh);
    adain_apply2<<<2048, 256>>>(khi, klo, vhi, vlo, m, sc, sh);

    attn_mma<<<dim3(8, 16, KVSPLIT), 256, ATTN_SMEM>>>(qhi, khi, vhi, vlo, m, prt, lsm);
    attn_reduce<<<256, 64>>>(prt, lsm, aohi, aolo);

    gemm_mma<1><<<dim3(8, 16), 256, GEMM_SMEM>>>(
        aohi, aolo, whi + 3 * WS, wlo + 3 * WS, bo, (float*)d_out,
        nullptr, nullptr, nullptr, nullptr, nullptr, nullptr, M, QD_);
}